// round 14
// baseline (speedup 1.0000x reference)
#include <cuda_runtime.h>
#include <cuda_fp16.h>
#include <math.h>
#include <stdint.h>

#define B_  4
#define T_  2048
#define C_  2048
#define NH  16
#define NKV 4
#define HD  128
#define KVW 1024
#define M_  (B_ * T_)   // 8192

// ---------------- scratch (no allocations allowed) ----------------
__device__ __half g_xh[(size_t)M_ * C_];        // x fp16
__device__ __half g_qh[(size_t)M_ * C_];        // q fp16 (normalized in place)
__device__ __half g_kh[(size_t)M_ * 512];       // k fp16 (normalized in place)
__device__ __half g_vh[(size_t)M_ * 512];       // v fp16
__device__ __half g_yh[(size_t)M_ * C_];        // attn out fp16
__device__ __half g_wqt[(size_t)C_ * C_];       // WqT  [N][K] fp16
__device__ __half g_wkvt[(size_t)KVW * C_];     // WkvT [N][K] fp16
__device__ __half g_wpt[(size_t)C_ * C_];       // WprojT [N][K] fp16

// ================= helpers =================
__device__ __forceinline__ uint32_t smem_to_u32(const void* p) {
    uint32_t a;
    asm("{ .reg .u64 t; cvta.to.shared.u64 t, %1; cvt.u32.u64 %0, t; }"
        : "=r"(a) : "l"(p));
    return a;
}
#define SWZ(off) ((off) ^ (((off) >> 3) & 0x70))

__device__ __forceinline__ void ldm4(uint32_t* r, uint32_t addr) {
    asm volatile("ldmatrix.sync.aligned.m8n8.x4.shared.b16 {%0,%1,%2,%3}, [%4];"
        : "=r"(r[0]), "=r"(r[1]), "=r"(r[2]), "=r"(r[3]) : "r"(addr));
}
__device__ __forceinline__ void ldm2(uint32_t* r, uint32_t addr) {
    asm volatile("ldmatrix.sync.aligned.m8n8.x2.shared.b16 {%0,%1}, [%2];"
        : "=r"(r[0]), "=r"(r[1]) : "r"(addr));
}
__device__ __forceinline__ void ldm4t(uint32_t* r, uint32_t addr) {
    asm volatile("ldmatrix.sync.aligned.m8n8.x4.trans.shared.b16 {%0,%1,%2,%3}, [%4];"
        : "=r"(r[0]), "=r"(r[1]), "=r"(r[2]), "=r"(r[3]) : "r"(addr));
}
__device__ __forceinline__ void mma_f16(float* c, const uint32_t* a, const uint32_t* b) {
    asm volatile("mma.sync.aligned.m16n8k16.row.col.f32.f16.f16.f32 "
        "{%0,%1,%2,%3}, {%4,%5,%6,%7}, {%8,%9}, {%0,%1,%2,%3};"
        : "+f"(c[0]), "+f"(c[1]), "+f"(c[2]), "+f"(c[3])
        : "r"(a[0]), "r"(a[1]), "r"(a[2]), "r"(a[3]), "r"(b[0]), "r"(b[1]));
}
__device__ __forceinline__ void cp16(uint32_t dst, const void* src) {
    asm volatile("cp.async.cg.shared.global [%0], [%1], 16;" :: "r"(dst), "l"(src));
}
#define CP_COMMIT() asm volatile("cp.async.commit_group;" ::: "memory")
#define CP_WAIT0()  asm volatile("cp.async.wait_group 0;" ::: "memory")
#define CP_WAIT1()  asm volatile("cp.async.wait_group 1;" ::: "memory")
#define CP_WAIT2()  asm volatile("cp.async.wait_group 2;" ::: "memory")

__device__ __forceinline__ uint32_t pack_h2(float x, float y) {
    __half2 t = __float22half2_rn(make_float2(x, y));
    return *(uint32_t*)&t;
}

// ================= staging kernels =================
__global__ void __launch_bounds__(512) convert_h(const float4* __restrict__ x,
                                                 uint2* __restrict__ hi, int n4)
{
    for (int i = blockIdx.x * 512 + threadIdx.x; i < n4; i += gridDim.x * 512) {
        float4 v = x[i];
        hi[i] = make_uint2(pack_h2(v.x, v.y), pack_h2(v.z, v.w));
    }
}

// W [K][N] fp32 -> WT [N][K] fp16
__global__ void __launch_bounds__(256) transpose_h(const float* __restrict__ W,
                                                   __half* __restrict__ Tt, int K, int N)
{
    __shared__ float t[32][33];
    int n0 = blockIdx.x * 32, k0 = blockIdx.y * 32;
    int tx = threadIdx.x, ty = threadIdx.y;
#pragma unroll
    for (int j = 0; j < 4; j++)
        t[ty + 8 * j][tx] = W[(size_t)(k0 + ty + 8 * j) * N + n0 + tx];
    __syncthreads();
#pragma unroll
    for (int j = 0; j < 4; j++)
        Tt[(size_t)(n0 + ty + 8 * j) * K + k0 + tx] = __float2half_rn(t[tx][ty + 8 * j]);
}

// ================= HMMA fp16 GEMM, 2-stage (R12-benched proven) =================
__device__ __forceinline__ void cp_panel(uint32_t dstBase, const __half* __restrict__ src,
                                         int ldk, int row0, int k0)
{
    int tid = threadIdx.x;
#pragma unroll
    for (int i = 0; i < 4; i++) {
        int l = tid + 256 * i;
        int r = l >> 3, ch = l & 7;
        cp16(dstBase + SWZ(r * 128 + ch * 16), src + (size_t)(row0 + r) * ldk + k0 + ch * 8);
    }
}

template<int FP16OUT>
__global__ void __launch_bounds__(256) gemm_mma(const __half* __restrict__ A,
                                                const __half* __restrict__ Bt,
                                                void* __restrict__ outp,
                                                int K, int No)
{
    extern __shared__ char sm[];
    uint32_t sb = smem_to_u32(sm);
    const int tid = threadIdx.x, wid = tid >> 5, lane = tid & 31;
    const int row0 = blockIdx.y * 128, col0 = blockIdx.x * 128;
    const int wm = (wid >> 2) * 64;
    const int wn = (wid & 3) * 32;

    float acc[4][4][4];
#pragma unroll
    for (int a = 0; a < 4; a++)
#pragma unroll
        for (int b = 0; b < 4; b++)
#pragma unroll
            for (int c = 0; c < 4; c++) acc[a][b][c] = 0.f;

    const int KIT = K >> 6;
#pragma unroll
    for (int p = 0; p < 2; p++) {
        uint32_t st = sb + p * 32768;
        cp_panel(st,         A,  K, row0, p * 64);
        cp_panel(st + 16384, Bt, K, col0, p * 64);
        CP_COMMIT();
    }

    for (int kc = 0; kc < KIT; kc++) {
        if (kc == KIT - 1) CP_WAIT0(); else CP_WAIT1();
        __syncthreads();

        uint32_t st = sb + (kc & 1) * 32768;
#pragma unroll
        for (int ks = 0; ks < 4; ks++) {
            uint32_t af[4][4], bf[4][2];
            const int arow = wm + (lane & 15);
            const int acol = ks * 32 + ((lane >> 4) & 1) * 16;
#pragma unroll
            for (int mt = 0; mt < 4; mt++)
                ldm4(af[mt], st + SWZ((uint32_t)(arow + mt * 16) * 128 + acol));
            const int brow = wn + (lane & 7);
            const int bcol = ks * 32 + ((lane >> 3) & 1) * 16;
#pragma unroll
            for (int nt = 0; nt < 4; nt++)
                ldm2(bf[nt], st + 16384 + SWZ((uint32_t)(brow + nt * 8) * 128 + bcol));
#pragma unroll
            for (int mt = 0; mt < 4; mt++)
#pragma unroll
                for (int nt = 0; nt < 4; nt++)
                    mma_f16(acc[mt][nt], af[mt], bf[nt]);
        }
        __syncthreads();

        if (kc + 2 < KIT) {
            uint32_t st2 = sb + (kc & 1) * 32768;
            int k0 = (kc + 2) * 64;
            cp_panel(st2,         A,  K, row0, k0);
            cp_panel(st2 + 16384, Bt, K, col0, k0);
            CP_COMMIT();
        }
    }

    const int r0 = row0 + wm + (lane >> 2);
    const int c0 = col0 + wn + (lane & 3) * 2;
    if (FP16OUT) {
        __half* o = (__half*)outp;
#pragma unroll
        for (int mt = 0; mt < 4; mt++)
#pragma unroll
            for (int nt = 0; nt < 4; nt++) {
                *(uint32_t*)(o + (size_t)(r0 + mt * 16) * No + c0 + nt * 8) =
                    pack_h2(acc[mt][nt][0], acc[mt][nt][1]);
                *(uint32_t*)(o + (size_t)(r0 + mt * 16 + 8) * No + c0 + nt * 8) =
                    pack_h2(acc[mt][nt][2], acc[mt][nt][3]);
            }
    } else {
        float* o = (float*)outp;
#pragma unroll
        for (int mt = 0; mt < 4; mt++)
#pragma unroll
            for (int nt = 0; nt < 4; nt++) {
                *(float2*)(o + (size_t)(r0 + mt * 16) * No + c0 + nt * 8) =
                    make_float2(acc[mt][nt][0], acc[mt][nt][1]);
                *(float2*)(o + (size_t)(r0 + mt * 16 + 8) * No + c0 + nt * 8) =
                    make_float2(acc[mt][nt][2], acc[mt][nt][3]);
            }
    }
}

// ================= fp16 in-place norms (R12-benched proven) =================
__global__ void __launch_bounds__(256) qnorm16()
{
    const size_t row = blockIdx.x;
    uint4* p = (uint4*)(g_qh + row * C_);
    uint4 v = p[threadIdx.x];
    __half2* h = (__half2*)&v;
    float ss = 0.f;
#pragma unroll
    for (int j = 0; j < 4; j++) {
        float2 f = __half22float2(h[j]);
        ss += f.x * f.x + f.y * f.y;
    }
#pragma unroll
    for (int off = 16; off; off >>= 1) ss += __shfl_xor_sync(0xffffffffu, ss, off);
    __shared__ float red[8];
    if ((threadIdx.x & 31) == 0) red[threadIdx.x >> 5] = ss;
    __syncthreads();
    float tot = red[0] + red[1] + red[2] + red[3] + red[4] + red[5] + red[6] + red[7];
    float sc = 0.08838834764831845f / (sqrtf(tot) + 1e-12f);
#pragma unroll
    for (int j = 0; j < 4; j++) {
        float2 f = __half22float2(h[j]);
        h[j] = __float22half2_rn(make_float2(f.x * sc, f.y * sc));
    }
    p[threadIdx.x] = v;
}

__global__ void __launch_bounds__(64) knorm16()
{
    const size_t row = blockIdx.x;
    uint4* p = (uint4*)(g_kh + row * 512);
    uint4 v = p[threadIdx.x];
    __half2* h = (__half2*)&v;
    float ss = 0.f;
#pragma unroll
    for (int j = 0; j < 4; j++) {
        float2 f = __half22float2(h[j]);
        ss += f.x * f.x + f.y * f.y;
    }
#pragma unroll
    for (int off = 16; off; off >>= 1) ss += __shfl_xor_sync(0xffffffffu, ss, off);
    __shared__ float red[2];
    if ((threadIdx.x & 31) == 0) red[threadIdx.x >> 5] = ss;
    __syncthreads();
    float sc = 1.f / (sqrtf(red[0] + red[1]) + 1e-12f);
#pragma unroll
    for (int j = 0; j < 4; j++) {
        float2 f = __half22float2(h[j]);
        h[j] = __float22half2_rn(make_float2(f.x * sc, f.y * sc));
    }
    p[threadIdx.x] = v;
}

// ================= HMMA flash attention: 2 heads/CTA (GQA KV reuse) =================
// 256 threads: warps 0-3 -> head 2*hp, warps 4-7 -> head 2*hp+1 (same kv group g).
// smem: Q 2x16KB + 3 KV stages x 32KB = 128KB. KV traffic HALVED vs 1-head blocks.
__device__ __forceinline__ void load_kv256(uint32_t dstBase, const __half* __restrict__ k,
                                           const __half* __restrict__ v)
{
    int tid = threadIdx.x;
#pragma unroll
    for (int i = 0; i < 4; i++) {
        int lin = tid + 256 * i;
        int r = lin >> 4, ch = lin & 15;
        cp16(dstBase + (ch >> 3) * 8192 + SWZ(r * 128 + (ch & 7) * 16),
             k + (size_t)r * 512 + ch * 8);
    }
#pragma unroll
    for (int i = 0; i < 4; i++) {
        int lin = tid + 256 * i;
        int r = lin >> 4, ch = lin & 15;
        cp16(dstBase + 16384 + (ch >> 3) * 8192 + SWZ(r * 128 + (ch & 7) * 16),
             v + (size_t)r * 512 + ch * 8);
    }
}

__global__ void __launch_bounds__(256) flash_mma_kernel()
{
    extern __shared__ char sm[];
    uint32_t sb = smem_to_u32(sm);
    const int tid = threadIdx.x, wid = tid >> 5, lane = tid & 31;
    const int half = wid >> 2;
    const int qt = blockIdx.x, hp = blockIdx.y, b = blockIdx.z;
    const int h = hp * 2 + half, g = hp >> 1;
    const int q0 = qt * 64, wm = (wid & 3) * 16;

    const __half* ksrc = g_kh + (size_t)b * T_ * 512 + g * HD;
    const __half* vsrc = g_vh + (size_t)b * T_ * 512 + g * HD;

    // both Q tiles (2048 x 16B chunks over 256 threads)
#pragma unroll
    for (int i = 0; i < 8; i++) {
        int lin = tid + 256 * i;
        int ht = lin >> 10;
        int rem = lin & 1023;
        int r = rem >> 4, ch = rem & 15;
        const __half* qs = g_qh + ((size_t)(b * T_ + q0 + r)) * C_ + (hp * 2 + ht) * HD;
        cp16(sb + ht * 16384 + (ch >> 3) * 8192 + SWZ(r * 128 + (ch & 7) * 16), qs + ch * 8);
    }
    CP_COMMIT();
    load_kv256(sb + 32768, ksrc, vsrc);
    CP_COMMIT();
    if (qt >= 1) {
        load_kv256(sb + 32768 + 32768, ksrc + 64 * 512, vsrc + 64 * 512);
        CP_COMMIT();
    }
    if (qt >= 1) CP_WAIT2(); else CP_WAIT1();   // Q ready
    __syncthreads();

    // hoist Q fragments from own half
    uint32_t aqr[8][4];
    const int arow = wm + (lane & 15);
    const uint32_t qbase = sb + half * 16384;
#pragma unroll
    for (int ks = 0; ks < 8; ks++)
        ldm4(aqr[ks], qbase + (ks >> 2) * 8192 +
                      SWZ(arow * 128 + (ks & 3) * 32 + ((lane >> 4) & 1) * 16));

    float o[16][4];
#pragma unroll
    for (int i = 0; i < 16; i++)
#pragma unroll
        for (int c = 0; c < 4; c++) o[i][c] = 0.f;
    float l0 = 0.f, l1 = 0.f;

    int stage = 0;
    for (int kt = 0; kt <= qt; kt++) {
        if (kt + 1 <= qt) CP_WAIT1(); else CP_WAIT0();
        __syncthreads();
        if (kt + 2 <= qt) {
            int ps = stage + 2; if (ps >= 3) ps -= 3;
            size_t off = (size_t)(kt + 2) * 64 * 512;
            load_kv256(sb + 32768 + ps * 32768, ksrc + off, vsrc + off);
            CP_COMMIT();
        }

        uint32_t Kb = sb + 32768 + stage * 32768;
        uint32_t Vb = Kb + 16384;
        if (++stage == 3) stage = 0;

        // ---- S = Q K^T ----
        float sf[8][4];
#pragma unroll
        for (int f = 0; f < 8; f++)
#pragma unroll
            for (int c = 0; c < 4; c++) sf[f][c] = 0.f;

#pragma unroll
        for (int ks = 0; ks < 8; ks++) {
            const int brow_l = (lane & 7) + 8 * ((lane >> 4) & 1);
            const int bcol   = (ks & 3) * 32 + ((lane >> 3) & 1) * 16;
#pragma unroll
            for (int nf = 0; nf < 4; nf++) {
                uint32_t kb[4];
                ldm4(kb, Kb + (ks >> 2) * 8192 + SWZ((nf * 16 + brow_l) * 128 + bcol));
                mma_f16(sf[2 * nf],     aqr[ks], kb);
                mma_f16(sf[2 * nf + 1], aqr[ks], kb + 2);
            }
        }

        if (kt == qt) {
            const int r0 = wm + (lane >> 2);
            const int cb = (lane & 3) * 2;
#pragma unroll
            for (int f = 0; f < 8; f++)
#pragma unroll
                for (int c = 0; c < 4; c++) {
                    int col = f * 8 + cb + (c & 1);
                    int row = r0 + (c >> 1) * 8;
                    if (col > row) sf[f][c] = -1e30f;
                }
        }

        // fixed-max softmax numerator (scores bounded by l2-norms)
#pragma unroll
        for (int f = 0; f < 8; f++) {
            sf[f][0] = __expf(sf[f][0]);
            sf[f][1] = __expf(sf[f][1]);
            sf[f][2] = __expf(sf[f][2]);
            sf[f][3] = __expf(sf[f][3]);
            l0 += sf[f][0] + sf[f][1];
            l1 += sf[f][2] + sf[f][3];
        }

        uint32_t pa[4][4];
#pragma unroll
        for (int kp = 0; kp < 4; kp++) {
            const int f0 = 2 * kp, f1 = 2 * kp + 1;
#pragma unroll
            for (int hf = 0; hf < 2; hf++) {
                pa[kp][hf]     = pack_h2(sf[f0][2 * hf], sf[f0][2 * hf + 1]);
                pa[kp][2 + hf] = pack_h2(sf[f1][2 * hf], sf[f1][2 * hf + 1]);
            }
        }

        const int krow = (lane & 7) + 8 * ((lane >> 3) & 1);
        const int nadd = 8 * (lane >> 4);
#pragma unroll
        for (int kp = 0; kp < 4; kp++) {
            const int kr = kp * 16 + krow;
#pragma unroll
            for (int nf = 0; nf < 8; nf++) {
                const int n0 = nf * 16;
                const uint32_t voff = ((uint32_t)(n0 >> 6)) * 8192 +
                                      SWZ(kr * 128 + ((n0 & 63) + nadd) * 2);
                uint32_t vb[4];
                ldm4t(vb, Vb + voff);
                mma_f16(o[2 * nf],     pa[kp], vb);
                mma_f16(o[2 * nf + 1], pa[kp], vb + 2);
            }
        }
    }

    l0 += __shfl_xor_sync(0xffffffffu, l0, 1);
    l0 += __shfl_xor_sync(0xffffffffu, l0, 2);
    l1 += __shfl_xor_sync(0xffffffffu, l1, 1);
    l1 += __shfl_xor_sync(0xffffffffu, l1, 2);
    float inv0 = 1.f / l0, inv1 = 1.f / l1;
    size_t row0 = (size_t)(b * T_ + q0 + wm + (lane >> 2));
    int colb = h * HD + (lane & 3) * 2;
#pragma unroll
    for (int nf = 0; nf < 16; nf++) {
        int col = colb + nf * 8;
        *(uint32_t*)(g_yh + row0 * C_ + col) =
            pack_h2(o[nf][0] * inv0, o[nf][1] * inv0);
        *(uint32_t*)(g_yh + (row0 + 8) * C_ + col) =
            pack_h2(o[nf][2] * inv1, o[nf][3] * inv1);
    }
}

// ================= launch =================
extern "C" void kernel_launch(void* const* d_in, const int* in_sizes, int n_in,
                              void* d_out, int out_size)
{
    const float* x     = (const float*)d_in[0];
    const float* Wq    = (const float*)d_in[1];
    const float* Wkv   = (const float*)d_in[2];
    const float* Wproj = (const float*)d_in[3];
    float* out = (float*)d_out;

    __half *xh, *qh, *kh, *vh, *yh, *wqt, *wkvt, *wpt;
    cudaGetSymbolAddress((void**)&xh,   g_xh);
    cudaGetSymbolAddress((void**)&qh,   g_qh);
    cudaGetSymbolAddress((void**)&kh,   g_kh);
    cudaGetSymbolAddress((void**)&vh,   g_vh);
    cudaGetSymbolAddress((void**)&yh,   g_yh);
    cudaGetSymbolAddress((void**)&wqt,  g_wqt);
    cudaGetSymbolAddress((void**)&wkvt, g_wkvt);
    cudaGetSymbolAddress((void**)&wpt,  g_wpt);

    const int GEMM_SMEM  = 2 * 32768;           // 64 KB -> 3 CTA/SM
    const int FLASH_SMEM = 32768 + 3 * 32768;   // 128 KB, 256 thr -> 8 warps/SM
    cudaFuncSetAttribute(gemm_mma<0>, cudaFuncAttributeMaxDynamicSharedMemorySize, GEMM_SMEM);
    cudaFuncSetAttribute(gemm_mma<1>, cudaFuncAttributeMaxDynamicSharedMemorySize, GEMM_SMEM);
    cudaFuncSetAttribute(flash_mma_kernel, cudaFuncAttributeMaxDynamicSharedMemorySize, FLASH_SMEM);

    // 1) stage inputs
    convert_h<<<2048, 512>>>((const float4*)x, (uint2*)xh, M_ * C_ / 4);
    transpose_h<<<dim3(C_ / 32, C_ / 32), dim3(32, 8)>>>(Wq, wqt, C_, C_);
    transpose_h<<<dim3(KVW / 32, C_ / 32), dim3(32, 8)>>>(Wkv, wkvt, C_, KVW);
    transpose_h<<<dim3(C_ / 32, C_ / 32), dim3(32, 8)>>>(Wproj, wpt, C_, C_);

    // 2) projections -> fp16 outputs (k and v via B row offsets in WkvT)
    gemm_mma<1><<<dim3(16, 64), 256, GEMM_SMEM>>>(xh, wqt,                     qh, C_, C_);
    gemm_mma<1><<<dim3(4,  64), 256, GEMM_SMEM>>>(xh, wkvt,                    kh, C_, 512);
    gemm_mma<1><<<dim3(4,  64), 256, GEMM_SMEM>>>(xh, wkvt + (size_t)512 * C_, vh, C_, 512);

    // 3) in-place fp16 l2 norms (q pre-scaled by 1/sqrt(HD))
    qnorm16<<<M_, 256>>>();
    knorm16<<<M_, 64>>>();

    // 4) flash attention, 2 heads/CTA -> yh
    flash_mma_kernel<<<dim3(T_ / 64, NH / 2, B_), 256, FLASH_SMEM>>>();

    // 5) out = y @ Wproj (fp32 out)
    gemm_mma<0><<<dim3(16, 64), 256, GEMM_SMEM>>>(yh, wpt, out, C_, C_);
}

// round 15
// speedup vs baseline: 1.0416x; 1.0416x over previous
#include <cuda_runtime.h>
#include <cuda_fp16.h>
#include <math.h>
#include <stdint.h>

#define B_  4
#define T_  2048
#define C_  2048
#define NH  16
#define NKV 4
#define HD  128
#define KVW 1024
#define M_  (B_ * T_)   // 8192

// ---------------- scratch (no allocations allowed) ----------------
__device__ __half g_xh[(size_t)M_ * C_];          // x fp16
__device__ __half g_qh[(size_t)M_ * C_];          // q fp16 (normalized in place)
__device__ __half g_kh[(size_t)M_ * 512];         // k fp16 (normalized in place)
__device__ __half g_vh[(size_t)M_ * 512];         // v fp16
__device__ __half g_yh[(size_t)M_ * C_];          // attn out fp16
__device__ __half g_wqkvt[(size_t)3072 * C_];     // [WqT (2048 rows) | WkvT (1024 rows)] [N][K]
__device__ __half g_wpt[(size_t)C_ * C_];         // WprojT [N][K]

// ================= helpers =================
__device__ __forceinline__ uint32_t smem_to_u32(const void* p) {
    uint32_t a;
    asm("{ .reg .u64 t; cvta.to.shared.u64 t, %1; cvt.u32.u64 %0, t; }"
        : "=r"(a) : "l"(p));
    return a;
}
#define SWZ(off) ((off) ^ (((off) >> 3) & 0x70))

__device__ __forceinline__ void ldm4(uint32_t* r, uint32_t addr) {
    asm volatile("ldmatrix.sync.aligned.m8n8.x4.shared.b16 {%0,%1,%2,%3}, [%4];"
        : "=r"(r[0]), "=r"(r[1]), "=r"(r[2]), "=r"(r[3]) : "r"(addr));
}
__device__ __forceinline__ void ldm2(uint32_t* r, uint32_t addr) {
    asm volatile("ldmatrix.sync.aligned.m8n8.x2.shared.b16 {%0,%1}, [%2];"
        : "=r"(r[0]), "=r"(r[1]) : "r"(addr));
}
__device__ __forceinline__ void ldm4t(uint32_t* r, uint32_t addr) {
    asm volatile("ldmatrix.sync.aligned.m8n8.x4.trans.shared.b16 {%0,%1,%2,%3}, [%4];"
        : "=r"(r[0]), "=r"(r[1]), "=r"(r[2]), "=r"(r[3]) : "r"(addr));
}
__device__ __forceinline__ void mma_f16(float* c, const uint32_t* a, const uint32_t* b) {
    asm volatile("mma.sync.aligned.m16n8k16.row.col.f32.f16.f16.f32 "
        "{%0,%1,%2,%3}, {%4,%5,%6,%7}, {%8,%9}, {%0,%1,%2,%3};"
        : "+f"(c[0]), "+f"(c[1]), "+f"(c[2]), "+f"(c[3])
        : "r"(a[0]), "r"(a[1]), "r"(a[2]), "r"(a[3]), "r"(b[0]), "r"(b[1]));
}
__device__ __forceinline__ void cp16(uint32_t dst, const void* src) {
    asm volatile("cp.async.cg.shared.global [%0], [%1], 16;" :: "r"(dst), "l"(src));
}
#define CP_COMMIT() asm volatile("cp.async.commit_group;" ::: "memory")
#define CP_WAIT0()  asm volatile("cp.async.wait_group 0;" ::: "memory")
#define CP_WAIT1()  asm volatile("cp.async.wait_group 1;" ::: "memory")
#define CP_WAIT2()  asm volatile("cp.async.wait_group 2;" ::: "memory")

__device__ __forceinline__ uint32_t pack_h2(float x, float y) {
    __half2 t = __float22half2_rn(make_float2(x, y));
    return *(uint32_t*)&t;
}

// ================= fused staging: x convert + 3 weight transposes =================
// blocks [0,2048): convert x -> xh
// blocks [2048,6144): Wq  transpose -> wqkvt rows [0,2048)
// blocks [6144,8192): Wkv transpose -> wqkvt rows [2048,3072)
// blocks [8192,12288): Wproj transpose -> wpt
__device__ __forceinline__ void transpose_tile(const float* __restrict__ W,
                                               __half* __restrict__ Tt,
                                               int K, int N, int n0, int k0, int tid)
{
    __shared__ float t[32][33];
    int tx = tid & 31, ty = tid >> 5;
#pragma unroll
    for (int j = 0; j < 4; j++)
        t[ty + 8 * j][tx] = W[(size_t)(k0 + ty + 8 * j) * N + n0 + tx];
    __syncthreads();
#pragma unroll
    for (int j = 0; j < 4; j++)
        Tt[(size_t)(n0 + ty + 8 * j) * K + k0 + tx] = __float2half_rn(t[tx][ty + 8 * j]);
}

__global__ void __launch_bounds__(256) stage_all(const float* __restrict__ x,
                                                 const float* __restrict__ Wq,
                                                 const float* __restrict__ Wkv,
                                                 const float* __restrict__ Wproj)
{
    const int bid = blockIdx.x, tid = threadIdx.x;
    if (bid < 2048) {
        const float4* src = (const float4*)x;
        uint2* dst = (uint2*)g_xh;
        const int n4 = M_ * C_ / 4;
        for (int i = bid * 256 + tid; i < n4; i += 2048 * 256) {
            float4 v = src[i];
            dst[i] = make_uint2(pack_h2(v.x, v.y), pack_h2(v.z, v.w));
        }
    } else if (bid < 6144) {
        int b = bid - 2048;                 // 64 x 64 tiles of Wq [2048][2048]
        transpose_tile(Wq, g_wqkvt, C_, C_, (b & 63) * 32, (b >> 6) * 32, tid);
    } else if (bid < 8192) {
        int b = bid - 6144;                 // 32 x 64 tiles of Wkv [2048][1024]
        transpose_tile(Wkv, g_wqkvt + (size_t)2048 * C_, C_, KVW,
                       (b & 31) * 32, (b >> 5) * 32, tid);
    } else {
        int b = bid - 8192;                 // 64 x 64 tiles of Wproj
        transpose_tile(Wproj, g_wpt, C_, C_, (b & 63) * 32, (b >> 6) * 32, tid);
    }
}

// ================= HMMA fp16 GEMM, 2-stage (R12 mainloop) =================
// MODE 0: fp32 out (outp, stride No). MODE 3: fused qkv epilogue select by col0.
__device__ __forceinline__ void cp_panel(uint32_t dstBase, const __half* __restrict__ src,
                                         int ldk, int row0, int k0)
{
    int tid = threadIdx.x;
#pragma unroll
    for (int i = 0; i < 4; i++) {
        int l = tid + 256 * i;
        int r = l >> 3, ch = l & 7;
        cp16(dstBase + SWZ(r * 128 + ch * 16), src + (size_t)(row0 + r) * ldk + k0 + ch * 8);
    }
}

template<int MODE>
__global__ void __launch_bounds__(256) gemm_mma(const __half* __restrict__ A,
                                                const __half* __restrict__ Bt,
                                                void* __restrict__ outp,
                                                int K, int No)
{
    extern __shared__ char sm[];
    uint32_t sb = smem_to_u32(sm);
    const int tid = threadIdx.x, wid = tid >> 5, lane = tid & 31;
    const int row0 = blockIdx.y * 128, col0 = blockIdx.x * 128;
    const int wm = (wid >> 2) * 64;
    const int wn = (wid & 3) * 32;

    float acc[4][4][4];
#pragma unroll
    for (int a = 0; a < 4; a++)
#pragma unroll
        for (int b = 0; b < 4; b++)
#pragma unroll
            for (int c = 0; c < 4; c++) acc[a][b][c] = 0.f;

    const int KIT = K >> 6;
#pragma unroll
    for (int p = 0; p < 2; p++) {
        uint32_t st = sb + p * 32768;
        cp_panel(st,         A,  K, row0, p * 64);
        cp_panel(st + 16384, Bt, K, col0, p * 64);
        CP_COMMIT();
    }

    for (int kc = 0; kc < KIT; kc++) {
        if (kc == KIT - 1) CP_WAIT0(); else CP_WAIT1();
        __syncthreads();

        uint32_t st = sb + (kc & 1) * 32768;
#pragma unroll
        for (int ks = 0; ks < 4; ks++) {
            uint32_t af[4][4], bf[4][2];
            const int arow = wm + (lane & 15);
            const int acol = ks * 32 + ((lane >> 4) & 1) * 16;
#pragma unroll
            for (int mt = 0; mt < 4; mt++)
                ldm4(af[mt], st + SWZ((uint32_t)(arow + mt * 16) * 128 + acol));
            const int brow = wn + (lane & 7);
            const int bcol = ks * 32 + ((lane >> 3) & 1) * 16;
#pragma unroll
            for (int nt = 0; nt < 4; nt++)
                ldm2(bf[nt], st + 16384 + SWZ((uint32_t)(brow + nt * 8) * 128 + bcol));
#pragma unroll
            for (int mt = 0; mt < 4; mt++)
#pragma unroll
                for (int nt = 0; nt < 4; nt++)
                    mma_f16(acc[mt][nt], af[mt], bf[nt]);
        }
        __syncthreads();

        if (kc + 2 < KIT) {
            uint32_t st2 = sb + (kc & 1) * 32768;
            int k0 = (kc + 2) * 64;
            cp_panel(st2,         A,  K, row0, k0);
            cp_panel(st2 + 16384, Bt, K, col0, k0);
            CP_COMMIT();
        }
    }

    const int r0 = row0 + wm + (lane >> 2);
    if (MODE == 0) {
        float* o = (float*)outp;
        const int c0 = col0 + wn + (lane & 3) * 2;
#pragma unroll
        for (int mt = 0; mt < 4; mt++)
#pragma unroll
            for (int nt = 0; nt < 4; nt++) {
                *(float2*)(o + (size_t)(r0 + mt * 16) * No + c0 + nt * 8) =
                    make_float2(acc[mt][nt][0], acc[mt][nt][1]);
                *(float2*)(o + (size_t)(r0 + mt * 16 + 8) * No + c0 + nt * 8) =
                    make_float2(acc[mt][nt][2], acc[mt][nt][3]);
            }
    } else {
        __half* o;
        int stride, cbase;
        if (col0 < 2048)      { o = g_qh; stride = C_;  cbase = col0; }
        else if (col0 < 2560) { o = g_kh; stride = 512; cbase = col0 - 2048; }
        else                  { o = g_vh; stride = 512; cbase = col0 - 2560; }
        const int c0 = cbase + wn + (lane & 3) * 2;
#pragma unroll
        for (int mt = 0; mt < 4; mt++)
#pragma unroll
            for (int nt = 0; nt < 4; nt++) {
                *(uint32_t*)(o + (size_t)(r0 + mt * 16) * stride + c0 + nt * 8) =
                    pack_h2(acc[mt][nt][0], acc[mt][nt][1]);
                *(uint32_t*)(o + (size_t)(r0 + mt * 16 + 8) * stride + c0 + nt * 8) =
                    pack_h2(acc[mt][nt][2], acc[mt][nt][3]);
            }
    }
}

// ================= fp16 in-place norms (R12 proven) =================
__global__ void __launch_bounds__(256) qnorm16()
{
    const size_t row = blockIdx.x;
    uint4* p = (uint4*)(g_qh + row * C_);
    uint4 v = p[threadIdx.x];
    __half2* h = (__half2*)&v;
    float ss = 0.f;
#pragma unroll
    for (int j = 0; j < 4; j++) {
        float2 f = __half22float2(h[j]);
        ss += f.x * f.x + f.y * f.y;
    }
#pragma unroll
    for (int off = 16; off; off >>= 1) ss += __shfl_xor_sync(0xffffffffu, ss, off);
    __shared__ float red[8];
    if ((threadIdx.x & 31) == 0) red[threadIdx.x >> 5] = ss;
    __syncthreads();
    float tot = red[0] + red[1] + red[2] + red[3] + red[4] + red[5] + red[6] + red[7];
    float sc = 0.08838834764831845f / (sqrtf(tot) + 1e-12f);
#pragma unroll
    for (int j = 0; j < 4; j++) {
        float2 f = __half22float2(h[j]);
        h[j] = __float22half2_rn(make_float2(f.x * sc, f.y * sc));
    }
    p[threadIdx.x] = v;
}

__global__ void __launch_bounds__(64) knorm16()
{
    const size_t row = blockIdx.x;
    uint4* p = (uint4*)(g_kh + row * 512);
    uint4 v = p[threadIdx.x];
    __half2* h = (__half2*)&v;
    float ss = 0.f;
#pragma unroll
    for (int j = 0; j < 4; j++) {
        float2 f = __half22float2(h[j]);
        ss += f.x * f.x + f.y * f.y;
    }
#pragma unroll
    for (int off = 16; off; off >>= 1) ss += __shfl_xor_sync(0xffffffffu, ss, off);
    __shared__ float red[2];
    if ((threadIdx.x & 31) == 0) red[threadIdx.x >> 5] = ss;
    __syncthreads();
    float sc = 1.f / (sqrtf(red[0] + red[1]) + 1e-12f);
#pragma unroll
    for (int j = 0; j < 4; j++) {
        float2 f = __half22float2(h[j]);
        h[j] = __float22half2_rn(make_float2(f.x * sc, f.y * sc));
    }
    p[threadIdx.x] = v;
}

// ================= HMMA flash attention (R12 proven, verbatim) =================
__device__ __forceinline__ void load_tile64(uint32_t dstBase, const __half* __restrict__ src,
                                            size_t stride)
{
    int tid = threadIdx.x;
#pragma unroll
    for (int i = 0; i < 8; i++) {
        int lin = tid + 128 * i;
        int r = lin >> 4, ch = lin & 15;
        cp16(dstBase + (ch >> 3) * 8192 + SWZ(r * 128 + (ch & 7) * 16),
             src + (size_t)r * stride + ch * 8);
    }
}

__global__ void __launch_bounds__(128) flash_mma_kernel()
{
    extern __shared__ char sm[];
    uint32_t sb = smem_to_u32(sm);
    const int tid = threadIdx.x, wid = tid >> 5, lane = tid & 31;
    const int qt = blockIdx.x, h = blockIdx.y, b = blockIdx.z, g = h >> 2;
    const int q0 = qt * 64, wm = wid * 16;

    const __half* qsrc = g_qh + ((size_t)(b * T_ + q0)) * C_ + h * HD;
    const __half* ksrc = g_kh + (size_t)b * T_ * 512 + g * HD;
    const __half* vsrc = g_vh + (size_t)b * T_ * 512 + g * HD;

    load_tile64(sb, qsrc, C_);
    CP_COMMIT();
    load_tile64(sb + 16384,         ksrc, 512);
    load_tile64(sb + 16384 + 16384, vsrc, 512);
    CP_COMMIT();
    if (qt >= 1) {
        uint32_t st = sb + 16384 + 32768;
        load_tile64(st,         ksrc + 64 * 512, 512);
        load_tile64(st + 16384, vsrc + 64 * 512, 512);
        CP_COMMIT();
    }
    if (qt >= 1) CP_WAIT2(); else CP_WAIT1();
    __syncthreads();

    uint32_t aqr[8][4];
    const int arow = wm + (lane & 15);
#pragma unroll
    for (int ks = 0; ks < 8; ks++)
        ldm4(aqr[ks], sb + (ks >> 2) * 8192 +
                      SWZ(arow * 128 + (ks & 3) * 32 + ((lane >> 4) & 1) * 16));

    float o[16][4];
#pragma unroll
    for (int i = 0; i < 16; i++)
#pragma unroll
        for (int c = 0; c < 4; c++) o[i][c] = 0.f;
    float l0 = 0.f, l1 = 0.f;

    int stage = 0;
    for (int kt = 0; kt <= qt; kt++) {
        if (kt + 1 <= qt) CP_WAIT1(); else CP_WAIT0();
        __syncthreads();
        if (kt + 2 <= qt) {
            int ps = stage + 2; if (ps >= 3) ps -= 3;
            uint32_t st = sb + 16384 + ps * 32768;
            size_t off = (size_t)(kt + 2) * 64 * 512;
            load_tile64(st,         ksrc + off, 512);
            load_tile64(st + 16384, vsrc + off, 512);
            CP_COMMIT();
        }

        uint32_t Kb = sb + 16384 + stage * 32768;
        uint32_t Vb = Kb + 16384;
        if (++stage == 3) stage = 0;

        float sf[8][4];
#pragma unroll
        for (int f = 0; f < 8; f++)
#pragma unroll
            for (int c = 0; c < 4; c++) sf[f][c] = 0.f;

#pragma unroll
        for (int ks = 0; ks < 8; ks++) {
            const int brow_l = (lane & 7) + 8 * ((lane >> 4) & 1);
            const int bcol   = (ks & 3) * 32 + ((lane >> 3) & 1) * 16;
#pragma unroll
            for (int nf = 0; nf < 4; nf++) {
                uint32_t kb[4];
                ldm4(kb, Kb + (ks >> 2) * 8192 + SWZ((nf * 16 + brow_l) * 128 + bcol));
                mma_f16(sf[2 * nf],     aqr[ks], kb);
                mma_f16(sf[2 * nf + 1], aqr[ks], kb + 2);
            }
        }

        if (kt == qt) {
            const int r0 = wm + (lane >> 2);
            const int cb = (lane & 3) * 2;
#pragma unroll
            for (int f = 0; f < 8; f++)
#pragma unroll
                for (int c = 0; c < 4; c++) {
                    int col = f * 8 + cb + (c & 1);
                    int row = r0 + (c >> 1) * 8;
                    if (col > row) sf[f][c] = -1e30f;
                }
        }

        // fixed-max softmax numerator (scores bounded by l2-norms)
#pragma unroll
        for (int f = 0; f < 8; f++) {
            sf[f][0] = __expf(sf[f][0]);
            sf[f][1] = __expf(sf[f][1]);
            sf[f][2] = __expf(sf[f][2]);
            sf[f][3] = __expf(sf[f][3]);
            l0 += sf[f][0] + sf[f][1];
            l1 += sf[f][2] + sf[f][3];
        }

        uint32_t pa[4][4];
#pragma unroll
        for (int kp = 0; kp < 4; kp++) {
            const int f0 = 2 * kp, f1 = 2 * kp + 1;
#pragma unroll
            for (int half = 0; half < 2; half++) {
                pa[kp][half]     = pack_h2(sf[f0][2 * half], sf[f0][2 * half + 1]);
                pa[kp][2 + half] = pack_h2(sf[f1][2 * half], sf[f1][2 * half + 1]);
            }
        }

        const int krow = (lane & 7) + 8 * ((lane >> 3) & 1);
        const int nadd = 8 * (lane >> 4);
#pragma unroll
        for (int kp = 0; kp < 4; kp++) {
            const int kr = kp * 16 + krow;
#pragma unroll
            for (int nf = 0; nf < 8; nf++) {
                const int n0 = nf * 16;
                const uint32_t voff = ((uint32_t)(n0 >> 6)) * 8192 +
                                      SWZ(kr * 128 + ((n0 & 63) + nadd) * 2);
                uint32_t vb[4];
                ldm4t(vb, Vb + voff);
                mma_f16(o[2 * nf],     pa[kp], vb);
                mma_f16(o[2 * nf + 1], pa[kp], vb + 2);
            }
        }
    }

    l0 += __shfl_xor_sync(0xffffffffu, l0, 1);
    l0 += __shfl_xor_sync(0xffffffffu, l0, 2);
    l1 += __shfl_xor_sync(0xffffffffu, l1, 1);
    l1 += __shfl_xor_sync(0xffffffffu, l1, 2);
    float inv0 = 1.f / l0, inv1 = 1.f / l1;
    size_t row0 = (size_t)(b * T_ + q0 + wm + (lane >> 2));
    int colb = h * HD + (lane & 3) * 2;
#pragma unroll
    for (int nf = 0; nf < 16; nf++) {
        int col = colb + nf * 8;
        *(uint32_t*)(g_yh + row0 * C_ + col) =
            pack_h2(o[nf][0] * inv0, o[nf][1] * inv0);
        *(uint32_t*)(g_yh + (row0 + 8) * C_ + col) =
            pack_h2(o[nf][2] * inv1, o[nf][3] * inv1);
    }
}

// ================= launch =================
extern "C" void kernel_launch(void* const* d_in, const int* in_sizes, int n_in,
                              void* d_out, int out_size)
{
    const float* x     = (const float*)d_in[0];
    const float* Wq    = (const float*)d_in[1];
    const float* Wkv   = (const float*)d_in[2];
    const float* Wproj = (const float*)d_in[3];
    float* out = (float*)d_out;

    __half *xh, *yh, *wqkvt, *wpt;
    cudaGetSymbolAddress((void**)&xh,    g_xh);
    cudaGetSymbolAddress((void**)&yh,    g_yh);
    cudaGetSymbolAddress((void**)&wqkvt, g_wqkvt);
    cudaGetSymbolAddress((void**)&wpt,   g_wpt);

    const int GEMM_SMEM  = 2 * 32768;           // 64 KB -> 3 CTA/SM
    const int FLASH_SMEM = 16384 + 3 * 32768;   // 112 KB -> 2 CTA/SM
    cudaFuncSetAttribute(gemm_mma<0>, cudaFuncAttributeMaxDynamicSharedMemorySize, GEMM_SMEM);
    cudaFuncSetAttribute(gemm_mma<3>, cudaFuncAttributeMaxDynamicSharedMemorySize, GEMM_SMEM);
    cudaFuncSetAttribute(flash_mma_kernel, cudaFuncAttributeMaxDynamicSharedMemorySize, FLASH_SMEM);

    // 1) fused staging: x convert + Wq/Wkv/Wproj transposes (one launch)
    stage_all<<<12288, 256>>>(x, Wq, Wkv, Wproj);

    // 2) fused q/k/v projection (one launch, stacked weights, epilogue select)
    gemm_mma<3><<<dim3(24, 64), 256, GEMM_SMEM>>>(xh, wqkvt, nullptr, C_, 0);

    // 3) in-place fp16 l2 norms (q pre-scaled by 1/sqrt(HD))
    qnorm16<<<M_, 256>>>();
    knorm16<<<M_, 64>>>();

    // 4) flash attention -> yh
    flash_mma_kernel<<<dim3(T_ / 64, NH, B_), 128, FLASH_SMEM>>>();

    // 5) out = y @ Wproj (fp32 out)
    gemm_mma<0><<<dim3(16, 64), 256, GEMM_SMEM>>>(yh, wpt, out, C_, C_);
}